// round 4
// baseline (speedup 1.0000x reference)
#include <cuda_runtime.h>

#define NROWS  524288
#define IND    64
#define OUTD   128
#define TILE   128
#define NTHREADS 256
#define NGRID  4096
#define TPC    (NROWS / TILE / NGRID)   // 1 tile per CTA

// Dynamic smem layout (floats):
//   c_s   [IND][OUTD]      : 64*128  = 8192   (centers, transposed; o contiguous)
//   x_s   [TILE][IND+4]    : 128*68  = 8704   (x tile, padded pitch)
//   rbf_s [TILE][OUTD]     : 128*128 = 16384
//   half_c2 [OUTD], half_x2 [TILE]
#define SMEM_FLOATS (IND*OUTD + TILE*(IND+4) + TILE*OUTD + OUTD + TILE)
#define SMEM_BYTES  (SMEM_FLOATS * 4)

typedef unsigned long long ull;

__device__ __forceinline__ ull pack2(float lo, float hi) {
    ull r; asm("mov.b64 %0, {%1, %2};" : "=l"(r) : "f"(lo), "f"(hi)); return r;
}
__device__ __forceinline__ ull fma2(ull a, ull b, ull c) {
    ull d; asm("fma.rn.f32x2 %0, %1, %2, %3;" : "=l"(d) : "l"(a), "l"(b), "l"(c)); return d;
}
__device__ __forceinline__ float2 unpack2(ull v) {
    float lo, hi; asm("mov.b64 {%0, %1}, %2;" : "=f"(lo), "=f"(hi) : "l"(v));
    float2 f; f.x = lo; f.y = hi; return f;
}

__global__ void zero_kernel(float* out) {
    int i = blockIdx.x * blockDim.x + threadIdx.x;
    if (i < OUTD * IND) out[i] = 0.0f;
}

__global__ __launch_bounds__(NTHREADS, 1)
void rbf_hist_kernel(const float* __restrict__ xg,
                     const float* __restrict__ cg,
                     float* __restrict__ out) {
    extern __shared__ float sm[];
    float (*c_s)[OUTD]   = (float(*)[OUTD])sm;
    float (*x_s)[IND+4]  = (float(*)[IND+4])(sm + IND*OUTD);
    float (*rbf_s)[OUTD] = (float(*)[OUTD])(sm + IND*OUTD + TILE*(IND+4));
    float* half_c2 = sm + IND*OUTD + TILE*(IND+4) + TILE*OUTD;
    float* half_x2 = half_c2 + OUTD;

    const int t = threadIdx.x;

    // Load centers transposed: c_s[i][o] = c[o][i]  (o contiguous per row)
    #pragma unroll
    for (int idx = t; idx < OUTD * IND; idx += NTHREADS) {
        int o = idx >> 6;
        int i = idx & 63;
        c_s[i][o] = cg[idx];
    }
    __syncthreads();
    if (t < OUTD) {
        float s = 0.f;
        #pragma unroll
        for (int k = 0; k < IND; k++) { float v = c_s[k][t]; s += v * v; }
        half_c2[t] = 0.5f * s;
    }

    // Phase-2 ownership: o in [o4,o4+4), i in [i8,i8+8) (i packed in pairs)
    const int o4  = (t & 31) * 4;
    const int i8  = (t >> 5) * 8;
    // Phase-1 ownership: 8x8 block of (n,o) (o packed in pairs)
    const int p1n = (t >> 4) * 8;
    const int p1o = (t & 15) * 8;

    ull hist2[4][4];
    #pragma unroll
    for (int a = 0; a < 4; a++)
        #pragma unroll
        for (int b = 0; b < 4; b++) hist2[a][b] = 0ull;

    for (int tile = 0; tile < TPC; tile++) {
        const int row0 = (blockIdx.x * TPC + tile) * TILE;

        // Load x tile: 128 rows x 64 f32 = 2048 float4, 8 per thread, coalesced
        const float4* xg4 = (const float4*)(xg + (size_t)row0 * IND);
        #pragma unroll
        for (int j = 0; j < 8; j++) {
            int idx = t + j * NTHREADS;       // 0..2047
            int r   = idx >> 4;               // 16 float4 per row
            int c4  = idx & 15;
            float4 v = xg4[idx];
            *(float4*)&x_s[r][c4 * 4] = v;
        }
        __syncthreads();

        if (t < TILE) {
            float s = 0.f;
            #pragma unroll
            for (int k = 0; k < IND; k++) { float v = x_s[t][k]; s += v * v; }
            half_x2[t] = 0.5f * s;
        }
        __syncthreads();

        // ---- Phase 1: S[n][o] = x_n . c_o  (8n x 4 packed-o register block) ----
        ull acc2[8][4];
        #pragma unroll
        for (int a = 0; a < 8; a++)
            #pragma unroll
            for (int b = 0; b < 4; b++) acc2[a][b] = 0ull;

        #pragma unroll 4
        for (int k = 0; k < IND; k++) {
            // c pairs loaded pre-packed straight from smem (o contiguous)
            ulonglong2 ca = *(const ulonglong2*)&c_s[k][p1o];      // o+0..3
            ulonglong2 cb = *(const ulonglong2*)&c_s[k][p1o + 4];  // o+4..7
            ull cv2[4] = {ca.x, ca.y, cb.x, cb.y};
            #pragma unroll
            for (int jn = 0; jn < 8; jn++) {
                float xv = x_s[p1n + jn][k];
                ull xb = pack2(xv, xv);
                #pragma unroll
                for (int jo = 0; jo < 4; jo++)
                    acc2[jn][jo] = fma2(xb, cv2[jo], acc2[jn][jo]);
            }
        }

        // rbf = exp(x.c - |x|^2/2 - |c|^2/2); store as packed float2
        #pragma unroll
        for (int jn = 0; jn < 8; jn++) {
            float hx = half_x2[p1n + jn];
            #pragma unroll
            for (int jo = 0; jo < 4; jo++) {
                float2 s2 = unpack2(acc2[jn][jo]);
                float2 r2;
                r2.x = __expf(s2.x - hx - half_c2[p1o + 2*jo]);
                r2.y = __expf(s2.y - hx - half_c2[p1o + 2*jo + 1]);
                *(float2*)&rbf_s[p1n + jn][p1o + 2*jo] = r2;
            }
        }
        __syncthreads();

        // ---- Phase 2: hist[o][i] += sum_n rbf[n][o] * x[n][i] (i packed) ----
        #pragma unroll 4
        for (int n = 0; n < TILE; n++) {
            float4 r4 = *(const float4*)&rbf_s[n][o4];            // 4 o values
            ulonglong2 xa = *(const ulonglong2*)&x_s[n][i8];      // i+0..3 packed
            ulonglong2 xb = *(const ulonglong2*)&x_s[n][i8 + 4];  // i+4..7 packed
            ull xv2[4] = {xa.x, xa.y, xb.x, xb.y};
            float rv[4] = {r4.x, r4.y, r4.z, r4.w};
            #pragma unroll
            for (int a = 0; a < 4; a++) {
                ull rb = pack2(rv[a], rv[a]);
                #pragma unroll
                for (int b = 0; b < 4; b++)
                    hist2[a][b] = fma2(rb, xv2[b], hist2[a][b]);
            }
        }
        __syncthreads();   // protect x_s / rbf_s before next tile
    }

    #pragma unroll
    for (int a = 0; a < 4; a++)
        #pragma unroll
        for (int b = 0; b < 4; b++) {
            float2 h = unpack2(hist2[a][b]);
            atomicAdd(&out[(o4 + a) * IND + i8 + 2*b],     h.x);
            atomicAdd(&out[(o4 + a) * IND + i8 + 2*b + 1], h.y);
        }
}

extern "C" void kernel_launch(void* const* d_in, const int* in_sizes, int n_in,
                              void* d_out, int out_size) {
    const float* x = (const float*)d_in[0];   // [524288, 64] f32
    const float* c = (const float*)d_in[1];   // [128, 64]    f32
    float* out = (float*)d_out;               // [128, 64]    f32

    cudaFuncSetAttribute(rbf_hist_kernel,
                         cudaFuncAttributeMaxDynamicSharedMemorySize, SMEM_BYTES);

    zero_kernel<<<(OUTD * IND + 255) / 256, 256>>>(out);
    rbf_hist_kernel<<<NGRID, NTHREADS, SMEM_BYTES>>>(x, c, out);
}

// round 6
// speedup vs baseline: 3.4516x; 3.4516x over previous
#include <cuda_runtime.h>
#include <cuda_bf16.h>
#include <cstdint>

#define NROWS  524288
#define IND    64
#define OUTD   128
#define TILE   128
#define NTHREADS 256
#define NGRID  148
#define NTILES (NROWS / TILE)   // 4096

#define PK 72     // pitch (bf16) of [row][64 k] tiles  -> 144B rows, conflict-free ldmatrix
#define PO 136    // pitch (bf16) of rbf [n][128 o]     -> 272B rows, conflict-free

// smem byte offsets
#define SM_XHI 0
#define SM_XLO (SM_XHI + TILE*PK*2)
#define SM_CHI (SM_XLO + TILE*PK*2)
#define SM_CLO (SM_CHI + TILE*PK*2)
#define SM_RHI (SM_CLO + TILE*PK*2)
#define SM_RLO (SM_RHI + TILE*PO*2)
#define SM_HX2 (SM_RLO + TILE*PO*2)
#define SM_HC2 (SM_HX2 + TILE*4)
#define SMEM_BYTES (SM_HC2 + OUTD*4)   // 144896 bytes

__device__ __forceinline__ uint32_t smem_u32(const void* p) {
    uint32_t a;
    asm("{ .reg .u64 t; cvta.to.shared.u64 t, %1; cvt.u32.u64 %0, t; }" : "=r"(a) : "l"(p));
    return a;
}
__device__ __forceinline__ void ldsm4(uint32_t* r, uint32_t addr) {
    asm volatile("ldmatrix.sync.aligned.m8n8.x4.shared.b16 {%0,%1,%2,%3}, [%4];"
        : "=r"(r[0]), "=r"(r[1]), "=r"(r[2]), "=r"(r[3]) : "r"(addr));
}
__device__ __forceinline__ void ldsm4t(uint32_t* r, uint32_t addr) {
    asm volatile("ldmatrix.sync.aligned.m8n8.x4.trans.shared.b16 {%0,%1,%2,%3}, [%4];"
        : "=r"(r[0]), "=r"(r[1]), "=r"(r[2]), "=r"(r[3]) : "r"(addr));
}
__device__ __forceinline__ void mma16816(float* d, const uint32_t* a, const uint32_t* b) {
    asm volatile("mma.sync.aligned.m16n8k16.row.col.f32.bf16.bf16.f32 "
        "{%0,%1,%2,%3}, {%4,%5,%6,%7}, {%8,%9}, {%0,%1,%2,%3};"
        : "+f"(d[0]), "+f"(d[1]), "+f"(d[2]), "+f"(d[3])
        : "r"(a[0]), "r"(a[1]), "r"(a[2]), "r"(a[3]), "r"(b[0]), "r"(b[1]));
}
__device__ __forceinline__ uint32_t bf2(float a, float b) {
    __nv_bfloat162 v = __floats2bfloat162_rn(a, b);
    return *reinterpret_cast<uint32_t*>(&v);
}
__device__ __forceinline__ float bfl(float a) {
    return __bfloat162float(__float2bfloat16_rn(a));
}

__global__ void zero_kernel(float* out) {
    int i = blockIdx.x * blockDim.x + threadIdx.x;
    if (i < OUTD * IND) out[i] = 0.0f;
}

__global__ __launch_bounds__(NTHREADS, 1)
void rbf_hist_kernel(const float* __restrict__ xg,
                     const float* __restrict__ cg,
                     float* __restrict__ out) {
    extern __shared__ char sm[];
    const uint32_t smb = smem_u32(sm);
    float* half_x2 = (float*)(sm + SM_HX2);
    float* half_c2 = (float*)(sm + SM_HC2);

    const int t    = threadIdx.x;
    const int w    = t >> 5;
    const int lane = t & 31;
    const int l8   = lane & 7;
    const int grp  = lane >> 3;
    const int qr   = lane >> 2;          // fragment row within 8
    const int q2   = (lane & 3) * 2;     // fragment col pair base

    // ---- load centers: bf16 hi/lo [o][k], + half|c|^2 (exact, shfl-reduced) ----
    {
        const float4* cg4 = (const float4*)cg;   // 128x64 f32 = 2048 float4
        #pragma unroll
        for (int j = 0; j < 8; j++) {
            int idx = t + j * NTHREADS;
            int r = idx >> 4, c4 = idx & 15;
            float4 v = cg4[idx];
            float h0 = bfl(v.x), h1 = bfl(v.y), h2 = bfl(v.z), h3 = bfl(v.w);
            uint2 hp = make_uint2(bf2(v.x, v.y), bf2(v.z, v.w));
            uint2 lp = make_uint2(bf2(v.x - h0, v.y - h1), bf2(v.z - h2, v.w - h3));
            *(uint2*)(sm + SM_CHI + (r * PK + 4 * c4) * 2) = hp;
            *(uint2*)(sm + SM_CLO + (r * PK + 4 * c4) * 2) = lp;
            float s = v.x*v.x + v.y*v.y + v.z*v.z + v.w*v.w;
            s += __shfl_xor_sync(0xffffffffu, s, 1);
            s += __shfl_xor_sync(0xffffffffu, s, 2);
            s += __shfl_xor_sync(0xffffffffu, s, 4);
            s += __shfl_xor_sync(0xffffffffu, s, 8);
            if ((lane & 15) == 0) half_c2[r] = 0.5f * s;
        }
    }

    // ---- per-thread ldmatrix base offsets (bytes) ----
    // phase-1 A: x[n][k] non-trans; rows n = 16w + l8 + (grp&1)*8, col k = (grp>>1)*8
    const uint32_t a1off = (uint32_t)(((16 * w + l8 + (grp & 1) * 8) * PK + (grp >> 1) * 8) * 2);
    // phase-1 B: c[o][k] non-trans; rows o = (grp>>1)*8 + l8 (+ot0*8), col k = (grp&1)*8 (+kk*16)
    const uint32_t b1off = (uint32_t)((((grp >> 1) * 8 + l8) * PK + (grp & 1) * 8) * 2);
    // phase-2 A: rbf[n][o] trans; rows n = (grp>>1)*8 + l8 (+kk*16), col o = 16w + (grp&1)*8
    const uint32_t a2off = (uint32_t)((((grp >> 1) * 8 + l8) * PO + 16 * w + (grp & 1) * 8) * 2);
    // phase-2 B: x[n][i] trans; rows n = kk2*32 + lane, col i = it*8
    const uint32_t b2off = (uint32_t)(lane * PK * 2);

    float acc2[8][4];
    #pragma unroll
    for (int a = 0; a < 8; a++)
        #pragma unroll
        for (int b = 0; b < 4; b++) acc2[a][b] = 0.f;

    for (int tile = blockIdx.x; tile < NTILES; tile += NGRID) {
        __syncthreads();   // previous phase-2 reads done before overwriting x / rbf

        // ---- load x tile: bf16 hi/lo [n][k], + half|x|^2 ----
        const float4* xg4 = (const float4*)(xg + (size_t)tile * TILE * IND);
        #pragma unroll
        for (int j = 0; j < 8; j++) {
            int idx = t + j * NTHREADS;
            int r = idx >> 4, c4 = idx & 15;
            float4 v = xg4[idx];
            float h0 = bfl(v.x), h1 = bfl(v.y), h2 = bfl(v.z), h3 = bfl(v.w);
            uint2 hp = make_uint2(bf2(v.x, v.y), bf2(v.z, v.w));
            uint2 lp = make_uint2(bf2(v.x - h0, v.y - h1), bf2(v.z - h2, v.w - h3));
            *(uint2*)(sm + SM_XHI + (r * PK + 4 * c4) * 2) = hp;
            *(uint2*)(sm + SM_XLO + (r * PK + 4 * c4) * 2) = lp;
            float s = v.x*v.x + v.y*v.y + v.z*v.z + v.w*v.w;
            s += __shfl_xor_sync(0xffffffffu, s, 1);
            s += __shfl_xor_sync(0xffffffffu, s, 2);
            s += __shfl_xor_sync(0xffffffffu, s, 4);
            s += __shfl_xor_sync(0xffffffffu, s, 8);
            if ((lane & 15) == 0) half_x2[r] = 0.5f * s;
        }
        __syncthreads();

        // ---- phase 1: D1[n][o] = x . c^T on tensor cores (hi/lo 3-pass) ----
        uint32_t Ah[4][4], Al[4][4];
        #pragma unroll
        for (int kk = 0; kk < 4; kk++) {
            ldsm4(Ah[kk], smb + SM_XHI + a1off + kk * 32);
            ldsm4(Al[kk], smb + SM_XLO + a1off + kk * 32);
        }
        float acc1[16][4];
        #pragma unroll
        for (int a = 0; a < 16; a++)
            #pragma unroll
            for (int b = 0; b < 4; b++) acc1[a][b] = 0.f;

        #pragma unroll
        for (int otp = 0; otp < 8; otp++) {
            #pragma unroll
            for (int kk = 0; kk < 4; kk++) {
                uint32_t bh[4], bl[4];
                uint32_t bo = b1off + (uint32_t)(otp * (16 * PK * 2) + kk * 32);
                ldsm4(bh, smb + SM_CHI + bo);
                ldsm4(bl, smb + SM_CLO + bo);
                mma16816(acc1[2*otp],   Ah[kk], &bh[0]);
                mma16816(acc1[2*otp+1], Ah[kk], &bh[2]);
                mma16816(acc1[2*otp],   Ah[kk], &bl[0]);
                mma16816(acc1[2*otp+1], Ah[kk], &bl[2]);
                mma16816(acc1[2*otp],   Al[kk], &bh[0]);
                mma16816(acc1[2*otp+1], Al[kk], &bh[2]);
            }
        }

        // ---- epilogue: rbf = exp(dot - |x|^2/2 - |c|^2/2), store bf16 hi/lo [n][o] ----
        {
            const int n0 = 16 * w + qr;
            const float hx0 = half_x2[n0];
            const float hx1 = half_x2[n0 + 8];
            #pragma unroll
            for (int ot = 0; ot < 16; ot++) {
                int o0 = ot * 8 + q2;
                float hc0 = half_c2[o0], hc1 = half_c2[o0 + 1];
                float v0 = __expf(acc1[ot][0] - hx0 - hc0);
                float v1 = __expf(acc1[ot][1] - hx0 - hc1);
                float v2 = __expf(acc1[ot][2] - hx1 - hc0);
                float v3 = __expf(acc1[ot][3] - hx1 - hc1);
                float h0 = bfl(v0), h1 = bfl(v1), h2 = bfl(v2), h3 = bfl(v3);
                *(uint32_t*)(sm + SM_RHI + (n0 * PO + o0) * 2)       = bf2(v0, v1);
                *(uint32_t*)(sm + SM_RLO + (n0 * PO + o0) * 2)       = bf2(v0 - h0, v1 - h1);
                *(uint32_t*)(sm + SM_RHI + ((n0 + 8) * PO + o0) * 2) = bf2(v2, v3);
                *(uint32_t*)(sm + SM_RLO + ((n0 + 8) * PO + o0) * 2) = bf2(v2 - h2, v3 - h3);
            }
        }
        __syncthreads();

        // ---- phase 2: hist[o][i] += rbf^T . x on tensor cores (hi/lo 3-pass) ----
        uint32_t A2h[8][4], A2l[8][4];
        #pragma unroll
        for (int kk = 0; kk < 8; kk++) {
            ldsm4t(A2h[kk], smb + SM_RHI + a2off + kk * (16 * PO * 2));
            ldsm4t(A2l[kk], smb + SM_RLO + a2off + kk * (16 * PO * 2));
        }
        #pragma unroll
        for (int it = 0; it < 8; it++) {
            #pragma unroll
            for (int kk2 = 0; kk2 < 4; kk2++) {
                uint32_t bh[4], bl[4];
                uint32_t bo = b2off + (uint32_t)(kk2 * (32 * PK * 2) + it * 16);
                ldsm4t(bh, smb + SM_XHI + bo);
                ldsm4t(bl, smb + SM_XLO + bo);
                int kk = 2 * kk2;
                mma16816(acc2[it], A2h[kk],     &bh[0]);
                mma16816(acc2[it], A2h[kk + 1], &bh[2]);
                mma16816(acc2[it], A2h[kk],     &bl[0]);
                mma16816(acc2[it], A2h[kk + 1], &bl[2]);
                mma16816(acc2[it], A2l[kk],     &bh[0]);
                mma16816(acc2[it], A2l[kk + 1], &bh[2]);
            }
        }
    }

    // ---- write out: D2 fragment (o = 16w + qr (+8), i = it*8 + q2 (+1)) ----
    const int o0 = 16 * w + qr;
    #pragma unroll
    for (int it = 0; it < 8; it++) {
        int i0 = it * 8 + q2;
        atomicAdd(&out[o0 * IND + i0],           acc2[it][0]);
        atomicAdd(&out[o0 * IND + i0 + 1],       acc2[it][1]);
        atomicAdd(&out[(o0 + 8) * IND + i0],     acc2[it][2]);
        atomicAdd(&out[(o0 + 8) * IND + i0 + 1], acc2[it][3]);
    }
}

extern "C" void kernel_launch(void* const* d_in, const int* in_sizes, int n_in,
                              void* d_out, int out_size) {
    const float* x = (const float*)d_in[0];   // [524288, 64] f32
    const float* c = (const float*)d_in[1];   // [128, 64]    f32
    float* out = (float*)d_out;               // [128, 64]    f32

    cudaFuncSetAttribute(rbf_hist_kernel,
                         cudaFuncAttributeMaxDynamicSharedMemorySize, SMEM_BYTES);

    zero_kernel<<<(OUTD * IND + 255) / 256, 256>>>(out);
    rbf_hist_kernel<<<NGRID, NTHREADS, SMEM_BYTES>>>(x, c, out);
}

// round 8
// speedup vs baseline: 3.5671x; 1.0335x over previous
#include <cuda_runtime.h>
#include <cuda_bf16.h>
#include <cstdint>

#define NROWS  524288
#define IND    64
#define OUTD   128
#define TILE   128
#define NTHREADS 256
#define NGRID  148
#define NTILES (NROWS / TILE)   // 4096

#define PK 72     // pitch (bf16) of [row][64 k] tiles  -> 144B rows, conflict-free ldmatrix
#define PO 136    // pitch (bf16) of rbf [n][128 o]     -> 272B rows, conflict-free

#define XBUF   (TILE*PK*2)          // 18432 bytes: one bf16 x tile
// smem byte offsets: [XHI0, XLO0, XHI1, XLO1, CHI, CLO, RHI, RLO, HX2(x2), HC2]
#define SM_X0   0                   // buf b: XHI at b*2*XBUF, XLO at b*2*XBUF+XBUF
#define SM_CHI  (4*XBUF)            // 73728
#define SM_CLO  (SM_CHI + XBUF)
#define SM_RHI  (SM_CHI + 2*XBUF)   // 110592
#define SM_RLO  (SM_RHI + TILE*PO*2)
#define SM_HX2  (SM_RHI + 2*TILE*PO*2)       // 2 buffers x 128 floats
#define SM_HC2  (SM_HX2 + 2*TILE*4)
#define SMEM_BYTES (SM_HC2 + OUTD*4)         // 181760 bytes

#define LOG2E 1.4426950408889634f

__device__ __forceinline__ uint32_t smem_u32(const void* p) {
    uint32_t a;
    asm("{ .reg .u64 t; cvta.to.shared.u64 t, %1; cvt.u32.u64 %0, t; }" : "=r"(a) : "l"(p));
    return a;
}
__device__ __forceinline__ void ldsm4(uint32_t* r, uint32_t addr) {
    asm volatile("ldmatrix.sync.aligned.m8n8.x4.shared.b16 {%0,%1,%2,%3}, [%4];"
        : "=r"(r[0]), "=r"(r[1]), "=r"(r[2]), "=r"(r[3]) : "r"(addr));
}
__device__ __forceinline__ void ldsm4t(uint32_t* r, uint32_t addr) {
    asm volatile("ldmatrix.sync.aligned.m8n8.x4.trans.shared.b16 {%0,%1,%2,%3}, [%4];"
        : "=r"(r[0]), "=r"(r[1]), "=r"(r[2]), "=r"(r[3]) : "r"(addr));
}
__device__ __forceinline__ void mma16816(float* d, const uint32_t* a, const uint32_t* b) {
    asm volatile("mma.sync.aligned.m16n8k16.row.col.f32.bf16.bf16.f32 "
        "{%0,%1,%2,%3}, {%4,%5,%6,%7}, {%8,%9}, {%0,%1,%2,%3};"
        : "+f"(d[0]), "+f"(d[1]), "+f"(d[2]), "+f"(d[3])
        : "r"(a[0]), "r"(a[1]), "r"(a[2]), "r"(a[3]), "r"(b[0]), "r"(b[1]));
}
__device__ __forceinline__ uint32_t bf2(float a, float b) {
    __nv_bfloat162 v = __floats2bfloat162_rn(a, b);
    return *reinterpret_cast<uint32_t*>(&v);
}
__device__ __forceinline__ float bfl(float a) {
    return __bfloat162float(__float2bfloat16_rn(a));
}

__global__ void zero_kernel(float* out) {
    int i = blockIdx.x * blockDim.x + threadIdx.x;
    if (i < OUTD * IND) out[i] = 0.0f;
}

// convert 32 fp32 (8 float4) held in regs -> bf16 hi/lo tile buf + scaled half|x|^2
__device__ __forceinline__ void convert_x(const float4* xr, char* sm, int buf,
                                          int t, int lane) {
    char* xhi = sm + buf * (2 * XBUF);
    char* xlo = xhi + XBUF;
    float* hx2 = (float*)(sm + SM_HX2) + buf * TILE;
    #pragma unroll
    for (int j = 0; j < 8; j++) {
        int idx = t + j * NTHREADS;
        int r = idx >> 4, c4 = idx & 15;
        float4 v = xr[j];
        float h0 = bfl(v.x), h1 = bfl(v.y), h2 = bfl(v.z), h3 = bfl(v.w);
        uint2 hp = make_uint2(bf2(v.x, v.y), bf2(v.z, v.w));
        uint2 lp = make_uint2(bf2(v.x - h0, v.y - h1), bf2(v.z - h2, v.w - h3));
        *(uint2*)(xhi + (r * PK + 4 * c4) * 2) = hp;
        *(uint2*)(xlo + (r * PK + 4 * c4) * 2) = lp;
        float s = v.x*v.x + v.y*v.y + v.z*v.z + v.w*v.w;
        s += __shfl_xor_sync(0xffffffffu, s, 1);
        s += __shfl_xor_sync(0xffffffffu, s, 2);
        s += __shfl_xor_sync(0xffffffffu, s, 4);
        s += __shfl_xor_sync(0xffffffffu, s, 8);
        if ((lane & 15) == 0) hx2[r] = 0.5f * LOG2E * s;
    }
}

__global__ __launch_bounds__(NTHREADS, 1)
void rbf_hist_kernel(const float* __restrict__ xg,
                     const float* __restrict__ cg,
                     float* __restrict__ out) {
    extern __shared__ char sm[];
    const uint32_t smb = smem_u32(sm);
    float* half_c2 = (float*)(sm + SM_HC2);

    const int t    = threadIdx.x;
    const int w    = t >> 5;
    const int lane = t & 31;
    const int l8   = lane & 7;
    const int grp  = lane >> 3;
    const int qr   = lane >> 2;
    const int q2   = (lane & 3) * 2;

    // ---- centers: bf16 hi/lo [o][k] + scaled half|c|^2 ----
    {
        const float4* cg4 = (const float4*)cg;
        #pragma unroll
        for (int j = 0; j < 8; j++) {
            int idx = t + j * NTHREADS;
            int r = idx >> 4, c4 = idx & 15;
            float4 v = cg4[idx];
            float h0 = bfl(v.x), h1 = bfl(v.y), h2 = bfl(v.z), h3 = bfl(v.w);
            uint2 hp = make_uint2(bf2(v.x, v.y), bf2(v.z, v.w));
            uint2 lp = make_uint2(bf2(v.x - h0, v.y - h1), bf2(v.z - h2, v.w - h3));
            *(uint2*)(sm + SM_CHI + (r * PK + 4 * c4) * 2) = hp;
            *(uint2*)(sm + SM_CLO + (r * PK + 4 * c4) * 2) = lp;
            float s = v.x*v.x + v.y*v.y + v.z*v.z + v.w*v.w;
            s += __shfl_xor_sync(0xffffffffu, s, 1);
            s += __shfl_xor_sync(0xffffffffu, s, 2);
            s += __shfl_xor_sync(0xffffffffu, s, 4);
            s += __shfl_xor_sync(0xffffffffu, s, 8);
            if ((lane & 15) == 0) half_c2[r] = 0.5f * LOG2E * s;
        }
    }

    // ---- ldmatrix base offsets (bytes) ----
    const uint32_t a1off = (uint32_t)(((16 * w + l8 + (grp & 1) * 8) * PK + (grp >> 1) * 8) * 2);
    const uint32_t b1off = (uint32_t)((((grp >> 1) * 8 + l8) * PK + (grp & 1) * 8) * 2);
    const uint32_t a2off = (uint32_t)((((grp >> 1) * 8 + l8) * PO + 16 * w + (grp & 1) * 8) * 2);
    const uint32_t b2off = (uint32_t)(lane * PK * 2);

    float acc2[8][4];
    #pragma unroll
    for (int a = 0; a < 8; a++)
        #pragma unroll
        for (int b = 0; b < 4; b++) acc2[a][b] = 0.f;

    // ---- prologue: load + convert first tile into buf 0 ----
    const int my_tiles = (NTILES - blockIdx.x + NGRID - 1) / NGRID;
    int tile = blockIdx.x;
    {
        const float4* xg4 = (const float4*)(xg + (size_t)tile * TILE * IND);
        float4 xr[8];
        #pragma unroll
        for (int j = 0; j < 8; j++) xr[j] = xg4[t + j * NTHREADS];
        convert_x(xr, sm, 0, t, lane);
    }
    __syncthreads();

    int cur = 0;
    for (int i = 0; i < my_tiles; i++) {
        const bool have_next = (i + 1 < my_tiles);
        const uint32_t xhi_b = smb + cur * (2 * XBUF);
        const uint32_t xlo_b = xhi_b + XBUF;
        const float* hx2 = (const float*)(sm + SM_HX2) + cur * TILE;

        // issue next tile's global loads early (hidden under phase-1 MMAs)
        float4 xr[8];
        if (have_next) {
            const float4* xg4n = (const float4*)(xg + (size_t)(tile + NGRID) * TILE * IND);
            #pragma unroll
            for (int j = 0; j < 8; j++) xr[j] = xg4n[t + j * NTHREADS];
        }

        // ---- phase 1: D1[n][o] = x . c^T (hi/lo 3-pass) ----
        uint32_t Ah[4][4], Al[4][4];
        #pragma unroll
        for (int kk = 0; kk < 4; kk++) {
            ldsm4(Ah[kk], xhi_b + a1off + kk * 32);
            ldsm4(Al[kk], xlo_b + a1off + kk * 32);
        }
        float acc1[16][4];
        #pragma unroll
        for (int a = 0; a < 16; a++)
            #pragma unroll
            for (int b = 0; b < 4; b++) acc1[a][b] = 0.f;

        #pragma unroll
        for (int otp = 0; otp < 8; otp++) {
            #pragma unroll
            for (int kk = 0; kk < 4; kk++) {
                uint32_t bh[4], bl[4];
                uint32_t bo = b1off + (uint32_t)(otp * (16 * PK * 2) + kk * 32);
                ldsm4(bh, smb + SM_CHI + bo);
                ldsm4(bl, smb + SM_CLO + bo);
                mma16816(acc1[2*otp],   Ah[kk], &bh[0]);
                mma16816(acc1[2*otp+1], Ah[kk], &bh[2]);
                mma16816(acc1[2*otp],   Ah[kk], &bl[0]);
                mma16816(acc1[2*otp+1], Ah[kk], &bl[2]);
                mma16816(acc1[2*otp],   Al[kk], &bh[0]);
                mma16816(acc1[2*otp+1], Al[kk], &bh[2]);
            }
        }

        // ---- epilogue: rbf = 2^(L*dot - hx' - hc'), store bf16 hi/lo ----
        {
            const int n0 = 16 * w + qr;
            const float hx0 = hx2[n0];
            const float hx1 = hx2[n0 + 8];
            #pragma unroll
            for (int ot = 0; ot < 16; ot++) {
                int o0 = ot * 8 + q2;
                float hc0 = half_c2[o0], hc1 = half_c2[o0 + 1];
                float v0 = exp2f(fmaf(acc1[ot][0], LOG2E, -hx0) - hc0);
                float v1 = exp2f(fmaf(acc1[ot][1], LOG2E, -hx0) - hc1);
                float v2 = exp2f(fmaf(acc1[ot][2], LOG2E, -hx1) - hc0);
                float v3 = exp2f(fmaf(acc1[ot][3], LOG2E, -hx1) - hc1);
                float h0 = bfl(v0), h1 = bfl(v1), h2 = bfl(v2), h3 = bfl(v3);
                *(uint32_t*)(sm + SM_RHI + (n0 * PO + o0) * 2)       = bf2(v0, v1);
                *(uint32_t*)(sm + SM_RLO + (n0 * PO + o0) * 2)       = bf2(v0 - h0, v1 - h1);
                *(uint32_t*)(sm + SM_RHI + ((n0 + 8) * PO + o0) * 2) = bf2(v2, v3);
                *(uint32_t*)(sm + SM_RLO + ((n0 + 8) * PO + o0) * 2) = bf2(v2 - h2, v3 - h3);
            }
        }
        __syncthreads();   // rbf visible; x[cur] still live for phase 2

        // convert next tile into the other buffer (overlaps phase-2 MMAs)
        if (have_next) convert_x(xr, sm, cur ^ 1, t, lane);

        // ---- phase 2: hist += rbf^T . x (hi/lo 3-pass), kk2-outer ----
        #pragma unroll
        for (int kk2 = 0; kk2 < 4; kk2++) {
            uint32_t A2h[2][4], A2l[2][4];
            ldsm4t(A2h[0], smb + SM_RHI + a2off + (2*kk2)     * (16 * PO * 2));
            ldsm4t(A2h[1], smb + SM_RHI + a2off + (2*kk2 + 1) * (16 * PO * 2));
            ldsm4t(A2l[0], smb + SM_RLO + a2off + (2*kk2)     * (16 * PO * 2));
            ldsm4t(A2l[1], smb + SM_RLO + a2off + (2*kk2 + 1) * (16 * PO * 2));
            #pragma unroll
            for (int it = 0; it < 8; it++) {
                uint32_t bh[4], bl[4];
                uint32_t bo = b2off + (uint32_t)(kk2 * (32 * PK * 2) + it * 16);
                ldsm4t(bh, xhi_b + bo);
                ldsm4t(bl, xlo_b + bo);
                mma16816(acc2[it], A2h[0], &bh[0]);
                mma16816(acc2[it], A2h[1], &bh[2]);
                mma16816(acc2[it], A2h[0], &bl[0]);
                mma16816(acc2[it], A2h[1], &bl[2]);
                mma16816(acc2[it], A2l[0], &bh[0]);
                mma16816(acc2[it], A2l[1], &bh[2]);
            }
        }
        __syncthreads();   // next buf ready; rbf free to overwrite

        cur ^= 1;
        tile += NGRID;
    }

    // ---- write out: o = 16w + qr (+8), i = it*8 + q2 (+1) ----
    const int o0 = 16 * w + qr;
    #pragma unroll
    for (int it = 0; it < 8; it++) {
        int i0 = it * 8 + q2;
        atomicAdd(&out[o0 * IND + i0],           acc2[it][0]);
        atomicAdd(&out[o0 * IND + i0 + 1],       acc2[it][1]);
        atomicAdd(&out[(o0 + 8) * IND + i0],     acc2[it][2]);
        atomicAdd(&out[(o0 + 8) * IND + i0 + 1], acc2[it][3]);
    }
}

extern "C" void kernel_launch(void* const* d_in, const int* in_sizes, int n_in,
                              void* d_out, int out_size) {
    const float* x = (const float*)d_in[0];   // [524288, 64] f32
    const float* c = (const float*)d_in[1];   // [128, 64]    f32
    float* out = (float*)d_out;               // [128, 64]    f32

    cudaFuncSetAttribute(rbf_hist_kernel,
                         cudaFuncAttributeMaxDynamicSharedMemorySize, SMEM_BYTES);

    zero_kernel<<<(OUTD * IND + 255) / 256, 256>>>(out);
    rbf_hist_kernel<<<NGRID, NTHREADS, SMEM_BYTES>>>(x, c, out);
}

// round 9
// speedup vs baseline: 3.6240x; 1.0160x over previous
#include <cuda_runtime.h>
#include <cuda_bf16.h>
#include <cstdint>

#define NROWS  524288
#define IND    64
#define OUTD   128
#define TILE   128
#define NTHREADS 512
#define NGRID  148
#define NTILES (NROWS / TILE)   // 4096

#define PK 72     // pitch (bf16) of [row][64 k] tiles
#define PO 136    // pitch (bf16) of rbf [n][128 o]

#define XBUF   (TILE*PK*2)          // 18432 bytes
#define SM_CHI  (4*XBUF)
#define SM_CLO  (SM_CHI + XBUF)
#define SM_RHI  (SM_CHI + 2*XBUF)
#define SM_RLO  (SM_RHI + TILE*PO*2)
#define SM_HX2  (SM_RHI + 2*TILE*PO*2)
#define SM_HC2  (SM_HX2 + 2*TILE*4)
#define SMEM_BYTES (SM_HC2 + OUTD*4)   // 181760 bytes

#define LOG2E 1.4426950408889634f

__device__ __forceinline__ uint32_t smem_u32(const void* p) {
    uint32_t a;
    asm("{ .reg .u64 t; cvta.to.shared.u64 t, %1; cvt.u32.u64 %0, t; }" : "=r"(a) : "l"(p));
    return a;
}
__device__ __forceinline__ void ldsm4(uint32_t* r, uint32_t addr) {
    asm volatile("ldmatrix.sync.aligned.m8n8.x4.shared.b16 {%0,%1,%2,%3}, [%4];"
        : "=r"(r[0]), "=r"(r[1]), "=r"(r[2]), "=r"(r[3]) : "r"(addr));
}
__device__ __forceinline__ void ldsm4t(uint32_t* r, uint32_t addr) {
    asm volatile("ldmatrix.sync.aligned.m8n8.x4.trans.shared.b16 {%0,%1,%2,%3}, [%4];"
        : "=r"(r[0]), "=r"(r[1]), "=r"(r[2]), "=r"(r[3]) : "r"(addr));
}
__device__ __forceinline__ void mma16816(float* d, const uint32_t* a, const uint32_t* b) {
    asm volatile("mma.sync.aligned.m16n8k16.row.col.f32.bf16.bf16.f32 "
        "{%0,%1,%2,%3}, {%4,%5,%6,%7}, {%8,%9}, {%0,%1,%2,%3};"
        : "+f"(d[0]), "+f"(d[1]), "+f"(d[2]), "+f"(d[3])
        : "r"(a[0]), "r"(a[1]), "r"(a[2]), "r"(a[3]), "r"(b[0]), "r"(b[1]));
}
__device__ __forceinline__ uint32_t bf2(float a, float b) {
    __nv_bfloat162 v = __floats2bfloat162_rn(a, b);
    return *reinterpret_cast<uint32_t*>(&v);
}
__device__ __forceinline__ float bfl(float a) {
    return __bfloat162float(__float2bfloat16_rn(a));
}

__global__ void zero_kernel(float* out) {
    int i = blockIdx.x * blockDim.x + threadIdx.x;
    if (i < OUTD * IND) out[i] = 0.0f;
}

// convert 16 fp32 (4 float4) held in regs -> bf16 hi/lo tile buf + scaled half|x|^2
__device__ __forceinline__ void convert_x(const float4* xr, char* sm, int buf,
                                          int t, int lane) {
    char* xhi = sm + buf * (2 * XBUF);
    char* xlo = xhi + XBUF;
    float* hx2 = (float*)(sm + SM_HX2) + buf * TILE;
    #pragma unroll
    for (int j = 0; j < 4; j++) {
        int idx = t + j * NTHREADS;
        int r = idx >> 4, c4 = idx & 15;
        float4 v = xr[j];
        float h0 = bfl(v.x), h1 = bfl(v.y), h2 = bfl(v.z), h3 = bfl(v.w);
        uint2 hp = make_uint2(bf2(v.x, v.y), bf2(v.z, v.w));
        uint2 lp = make_uint2(bf2(v.x - h0, v.y - h1), bf2(v.z - h2, v.w - h3));
        *(uint2*)(xhi + (r * PK + 4 * c4) * 2) = hp;
        *(uint2*)(xlo + (r * PK + 4 * c4) * 2) = lp;
        float s = v.x*v.x + v.y*v.y + v.z*v.z + v.w*v.w;
        s += __shfl_xor_sync(0xffffffffu, s, 1);
        s += __shfl_xor_sync(0xffffffffu, s, 2);
        s += __shfl_xor_sync(0xffffffffu, s, 4);
        s += __shfl_xor_sync(0xffffffffu, s, 8);
        if ((lane & 15) == 0) hx2[r] = 0.5f * LOG2E * s;
    }
}

__global__ __launch_bounds__(NTHREADS, 1)
void rbf_hist_kernel(const float* __restrict__ xg,
                     const float* __restrict__ cg,
                     float* __restrict__ out) {
    extern __shared__ char sm[];
    const uint32_t smb = smem_u32(sm);
    float* half_c2 = (float*)(sm + SM_HC2);

    const int t    = threadIdx.x;
    const int w    = t >> 5;
    const int lane = t & 31;
    const int l8   = lane & 7;
    const int grp  = lane >> 3;
    const int qr   = lane >> 2;
    const int q2   = (lane & 3) * 2;
    const int wo   = w & 7;      // n-block (phase1) / o-block (phase2)
    const int wh   = w >> 3;     // o-half (phase1) / i-half (phase2)

    // ---- centers: bf16 hi/lo [o][k] + scaled half|c|^2 ----
    {
        const float4* cg4 = (const float4*)cg;
        #pragma unroll
        for (int j = 0; j < 4; j++) {
            int idx = t + j * NTHREADS;
            int r = idx >> 4, c4 = idx & 15;
            float4 v = cg4[idx];
            float h0 = bfl(v.x), h1 = bfl(v.y), h2 = bfl(v.z), h3 = bfl(v.w);
            uint2 hp = make_uint2(bf2(v.x, v.y), bf2(v.z, v.w));
            uint2 lp = make_uint2(bf2(v.x - h0, v.y - h1), bf2(v.z - h2, v.w - h3));
            *(uint2*)(sm + SM_CHI + (r * PK + 4 * c4) * 2) = hp;
            *(uint2*)(sm + SM_CLO + (r * PK + 4 * c4) * 2) = lp;
            float s = v.x*v.x + v.y*v.y + v.z*v.z + v.w*v.w;
            s += __shfl_xor_sync(0xffffffffu, s, 1);
            s += __shfl_xor_sync(0xffffffffu, s, 2);
            s += __shfl_xor_sync(0xffffffffu, s, 4);
            s += __shfl_xor_sync(0xffffffffu, s, 8);
            if ((lane & 15) == 0) half_c2[r] = 0.5f * LOG2E * s;
        }
    }

    // ---- ldmatrix base offsets (bytes) ----
    // phase-1 A: x[n][k]; n = 16*wo + l8 + (grp&1)*8, k = (grp>>1)*8
    const uint32_t a1off = (uint32_t)(((16 * wo + l8 + (grp & 1) * 8) * PK + (grp >> 1) * 8) * 2);
    // phase-1 B: c[o][k]; o = wh*64 + otp*16 + (grp>>1)*8 + l8, k = (grp&1)*8 (+kk*16)
    const uint32_t b1off = (uint32_t)(((wh * 64 + (grp >> 1) * 8 + l8) * PK + (grp & 1) * 8) * 2);
    // phase-2 A: rbf[n][o] trans; n = kk*16 + (grp>>1)*8 + l8, o = 16*wo + (grp&1)*8
    const uint32_t a2off = (uint32_t)((((grp >> 1) * 8 + l8) * PO + 16 * wo + (grp & 1) * 8) * 2);
    // phase-2 B: x[n][i] trans; n = kk2*32 + lane, i = wh*32 + it*8
    const uint32_t b2off = (uint32_t)((lane * PK + wh * 32) * 2);

    float acc2[4][4];
    #pragma unroll
    for (int a = 0; a < 4; a++)
        #pragma unroll
        for (int b = 0; b < 4; b++) acc2[a][b] = 0.f;

    // ---- prologue: load + convert first tile into buf 0 ----
    const int my_tiles = (NTILES - blockIdx.x + NGRID - 1) / NGRID;
    int tile = blockIdx.x;
    {
        const float4* xg4 = (const float4*)(xg + (size_t)tile * TILE * IND);
        float4 xr[4];
        #pragma unroll
        for (int j = 0; j < 4; j++) xr[j] = xg4[t + j * NTHREADS];
        convert_x(xr, sm, 0, t, lane);
    }
    __syncthreads();

    int cur = 0;
    for (int i = 0; i < my_tiles; i++) {
        const bool have_next = (i + 1 < my_tiles);
        const uint32_t xhi_b = smb + cur * (2 * XBUF);
        const uint32_t xlo_b = xhi_b + XBUF;
        const float* hx2 = (const float*)(sm + SM_HX2) + cur * TILE;

        // issue next tile's global loads early (hidden under phase-1 MMAs)
        float4 xr[4];
        if (have_next) {
            const float4* xg4n = (const float4*)(xg + (size_t)(tile + NGRID) * TILE * IND);
            #pragma unroll
            for (int j = 0; j < 4; j++) xr[j] = xg4n[t + j * NTHREADS];
        }

        // ---- phase 1: D1[16n x 64o] = x . c^T (hi/lo 3-pass) ----
        uint32_t Ah[4][4], Al[4][4];
        #pragma unroll
        for (int kk = 0; kk < 4; kk++) {
            ldsm4(Ah[kk], xhi_b + a1off + kk * 32);
            ldsm4(Al[kk], xlo_b + a1off + kk * 32);
        }
        float acc1[8][4];
        #pragma unroll
        for (int a = 0; a < 8; a++)
            #pragma unroll
            for (int b = 0; b < 4; b++) acc1[a][b] = 0.f;

        #pragma unroll
        for (int otp = 0; otp < 4; otp++) {
            #pragma unroll
            for (int kk = 0; kk < 4; kk++) {
                uint32_t bh[4], bl[4];
                uint32_t bo = b1off + (uint32_t)(otp * (16 * PK * 2) + kk * 32);
                ldsm4(bh, smb + SM_CHI + bo);
                ldsm4(bl, smb + SM_CLO + bo);
                mma16816(acc1[2*otp],   Ah[kk], &bh[0]);
                mma16816(acc1[2*otp+1], Ah[kk], &bh[2]);
                mma16816(acc1[2*otp],   Ah[kk], &bl[0]);
                mma16816(acc1[2*otp+1], Ah[kk], &bl[2]);
                mma16816(acc1[2*otp],   Al[kk], &bh[0]);
                mma16816(acc1[2*otp+1], Al[kk], &bh[2]);
            }
        }

        // ---- epilogue: rbf = 2^(L*dot - hx' - hc'), store bf16 hi/lo ----
        {
            const int n0 = 16 * wo + qr;
            const float hx0 = hx2[n0];
            const float hx1 = hx2[n0 + 8];
            #pragma unroll
            for (int ot = 0; ot < 8; ot++) {
                int o0 = wh * 64 + ot * 8 + q2;
                float hc0 = half_c2[o0], hc1 = half_c2[o0 + 1];
                float v0 = exp2f(fmaf(acc1[ot][0], LOG2E, -hx0) - hc0);
                float v1 = exp2f(fmaf(acc1[ot][1], LOG2E, -hx0) - hc1);
                float v2 = exp2f(fmaf(acc1[ot][2], LOG2E, -hx1) - hc0);
                float v3 = exp2f(fmaf(acc1[ot][3], LOG2E, -hx1) - hc1);
                float h0 = bfl(v0), h1 = bfl(v1), h2 = bfl(v2), h3 = bfl(v3);
                *(uint32_t*)(sm + SM_RHI + (n0 * PO + o0) * 2)       = bf2(v0, v1);
                *(uint32_t*)(sm + SM_RLO + (n0 * PO + o0) * 2)       = bf2(v0 - h0, v1 - h1);
                *(uint32_t*)(sm + SM_RHI + ((n0 + 8) * PO + o0) * 2) = bf2(v2, v3);
                *(uint32_t*)(sm + SM_RLO + ((n0 + 8) * PO + o0) * 2) = bf2(v2 - h2, v3 - h3);
            }
        }
        __syncthreads();   // rbf visible; x[cur] still live for phase 2

        // convert next tile into the other buffer (overlaps phase-2 MMAs)
        if (have_next) convert_x(xr, sm, cur ^ 1, t, lane);

        // ---- phase 2: hist[16o x 32i] += rbf^T . x (hi/lo 3-pass) ----
        #pragma unroll
        for (int kk2 = 0; kk2 < 4; kk2++) {
            uint32_t A2h[2][4], A2l[2][4];
            ldsm4t(A2h[0], smb + SM_RHI + a2off + (2*kk2)     * (16 * PO * 2));
            ldsm4t(A2h[1], smb + SM_RHI + a2off + (2*kk2 + 1) * (16 * PO * 2));
            ldsm4t(A2l[0], smb + SM_RLO + a2off + (2*kk2)     * (16 * PO * 2));
            ldsm4t(A2l[1], smb + SM_RLO + a2off + (2*kk2 + 1) * (16 * PO * 2));
            #pragma unroll
            for (int it = 0; it < 4; it++) {
                uint32_t bh[4], bl[4];
                uint32_t bo = b2off + (uint32_t)(kk2 * (32 * PK * 2) + it * 16);
                ldsm4t(bh, xhi_b + bo);
                ldsm4t(bl, xlo_b + bo);
                mma16816(acc2[it], A2h[0], &bh[0]);
                mma16816(acc2[it], A2h[1], &bh[2]);
                mma16816(acc2[it], A2h[0], &bl[0]);
                mma16816(acc2[it], A2h[1], &bl[2]);
                mma16816(acc2[it], A2l[0], &bh[0]);
                mma16816(acc2[it], A2l[1], &bh[2]);
            }
        }
        __syncthreads();   // next buf ready; rbf free to overwrite

        cur ^= 1;
        tile += NGRID;
    }

    // ---- write out: o = 16*wo + qr (+8), i = wh*32 + it*8 + q2 (+1) ----
    const int o0 = 16 * wo + qr;
    #pragma unroll
    for (int it = 0; it < 4; it++) {
        int i0 = wh * 32 + it * 8 + q2;
        atomicAdd(&out[o0 * IND + i0],           acc2[it][0]);
        atomicAdd(&out[o0 * IND + i0 + 1],       acc2[it][1]);
        atomicAdd(&out[(o0 + 8) * IND + i0],     acc2[it][2]);
        atomicAdd(&out[(o0 + 8) * IND + i0 + 1], acc2[it][3]);
    }
}

extern "C" void kernel_launch(void* const* d_in, const int* in_sizes, int n_in,
                              void* d_out, int out_size) {
    const float* x = (const float*)d_in[0];   // [524288, 64] f32
    const float* c = (const float*)d_in[1];   // [128, 64]    f32
    float* out = (float*)d_out;               // [128, 64]    f32

    cudaFuncSetAttribute(rbf_hist_kernel,
                         cudaFuncAttributeMaxDynamicSharedMemorySize, SMEM_BYTES);

    zero_kernel<<<(OUTD * IND + 255) / 256, 256>>>(out);
    rbf_hist_kernel<<<NGRID, NTHREADS, SMEM_BYTES>>>(x, c, out);
}

// round 13
// speedup vs baseline: 4.1400x; 1.1424x over previous
#include <cuda_runtime.h>
#include <cuda_bf16.h>
#include <cuda_fp16.h>
#include <cstdint>

#define NROWS  524288
#define IND    64
#define OUTD   128
#define TILE   128
#define NTHREADS 512
#define NGRID  148
#define NTILES (NROWS / TILE)   // 4096

#define PK 72     // pitch (elements) of [row][64 k] tiles (b16)
#define PO 136    // pitch (elements) of rbf [n][128 o] (b16)

#define XBUF    (TILE*PK*2)            // 18432 bytes per b16 x tile
// layout: XHI0 XLO0 XHI1 XLO1 | XF16_0 XF16_1 | CHI CLO | RF16 | MPART | MRUN SCALE HX2 HC2
#define SM_XF16  (4*XBUF)              // 73728
#define SM_CHI   (SM_XF16 + 2*XBUF)    // 110592
#define SM_CLO   (SM_CHI + XBUF)
#define SM_RF16  (SM_CHI + 2*XBUF)     // 147456 ; fp16 rbf tile (TILE*PO*2 = 34816)
#define SM_MPART (SM_RF16 + TILE*PO*2) // 182272 ; [8][128] f32 = 4096
#define SM_MRUN  (SM_MPART + 4096)     // 128 f32
#define SM_SCALE (SM_MRUN + 512)       // 128 f32
#define SM_HX2   (SM_SCALE + 512)      // 2*128 f32
#define SM_HC2   (SM_HX2 + 2*TILE*4)   // 128 f32
#define SMEM_BYTES (SM_HC2 + OUTD*4)   // ~188928 bytes

#define LOG2E 1.4426950408889634f

__device__ __forceinline__ uint32_t smem_u32(const void* p) {
    uint32_t a;
    asm("{ .reg .u64 t; cvta.to.shared.u64 t, %1; cvt.u32.u64 %0, t; }" : "=r"(a) : "l"(p));
    return a;
}
__device__ __forceinline__ void ldsm4(uint32_t* r, uint32_t addr) {
    asm volatile("ldmatrix.sync.aligned.m8n8.x4.shared.b16 {%0,%1,%2,%3}, [%4];"
        : "=r"(r[0]), "=r"(r[1]), "=r"(r[2]), "=r"(r[3]) : "r"(addr));
}
__device__ __forceinline__ void ldsm4t(uint32_t* r, uint32_t addr) {
    asm volatile("ldmatrix.sync.aligned.m8n8.x4.trans.shared.b16 {%0,%1,%2,%3}, [%4];"
        : "=r"(r[0]), "=r"(r[1]), "=r"(r[2]), "=r"(r[3]) : "r"(addr));
}
__device__ __forceinline__ void mma_bf16(float* d, const uint32_t* a, const uint32_t* b) {
    asm volatile("mma.sync.aligned.m16n8k16.row.col.f32.bf16.bf16.f32 "
        "{%0,%1,%2,%3}, {%4,%5,%6,%7}, {%8,%9}, {%0,%1,%2,%3};"
        : "+f"(d[0]), "+f"(d[1]), "+f"(d[2]), "+f"(d[3])
        : "r"(a[0]), "r"(a[1]), "r"(a[2]), "r"(a[3]), "r"(b[0]), "r"(b[1]));
}
__device__ __forceinline__ void mma_f16(float* d, const uint32_t* a, const uint32_t* b) {
    asm volatile("mma.sync.aligned.m16n8k16.row.col.f32.f16.f16.f32 "
        "{%0,%1,%2,%3}, {%4,%5,%6,%7}, {%8,%9}, {%0,%1,%2,%3};"
        : "+f"(d[0]), "+f"(d[1]), "+f"(d[2]), "+f"(d[3])
        : "r"(a[0]), "r"(a[1]), "r"(a[2]), "r"(a[3]), "r"(b[0]), "r"(b[1]));
}
__device__ __forceinline__ uint32_t bf2(float a, float b) {
    __nv_bfloat162 v = __floats2bfloat162_rn(a, b);
    return *reinterpret_cast<uint32_t*>(&v);
}
__device__ __forceinline__ uint32_t hf2(float a, float b) {
    __half2 v = __floats2half2_rn(a, b);
    return *reinterpret_cast<uint32_t*>(&v);
}
__device__ __forceinline__ float bfl(float a) {
    return __bfloat162float(__float2bfloat16_rn(a));
}

__global__ void zero_kernel(float* out) {
    int i = blockIdx.x * blockDim.x + threadIdx.x;
    if (i < OUTD * IND) out[i] = 0.0f;
}

// convert 16 fp32 (4 float4) -> bf16 hi/lo + fp16 tiles + scaled half|x|^2
__device__ __forceinline__ void convert_x(const float4* xr, char* sm, int buf,
                                          int t, int lane) {
    char* xhi = sm + buf * (2 * XBUF);
    char* xlo = xhi + XBUF;
    char* xf  = sm + SM_XF16 + buf * XBUF;
    float* hx2 = (float*)(sm + SM_HX2) + buf * TILE;
    #pragma unroll
    for (int j = 0; j < 4; j++) {
        int idx = t + j * NTHREADS;
        int r = idx >> 4, c4 = idx & 15;
        float4 v = xr[j];
        float h0 = bfl(v.x), h1 = bfl(v.y), h2 = bfl(v.z), h3 = bfl(v.w);
        uint32_t eo = (uint32_t)((r * PK + 4 * c4) * 2);
        *(uint2*)(xhi + eo) = make_uint2(bf2(v.x, v.y), bf2(v.z, v.w));
        *(uint2*)(xlo + eo) = make_uint2(bf2(v.x - h0, v.y - h1), bf2(v.z - h2, v.w - h3));
        *(uint2*)(xf  + eo) = make_uint2(hf2(v.x, v.y), hf2(v.z, v.w));
        float s = v.x*v.x + v.y*v.y + v.z*v.z + v.w*v.w;
        s += __shfl_xor_sync(0xffffffffu, s, 1);
        s += __shfl_xor_sync(0xffffffffu, s, 2);
        s += __shfl_xor_sync(0xffffffffu, s, 4);
        s += __shfl_xor_sync(0xffffffffu, s, 8);
        if ((lane & 15) == 0) hx2[r] = 0.5f * LOG2E * s;
    }
}

__global__ __launch_bounds__(NTHREADS, 1)
void rbf_hist_kernel(const float* __restrict__ xg,
                     const float* __restrict__ cg,
                     float* __restrict__ out) {
    extern __shared__ char sm[];
    const uint32_t smb = smem_u32(sm);
    float* half_c2 = (float*)(sm + SM_HC2);
    float* m_part  = (float*)(sm + SM_MPART);   // [8][128]
    float* m_run   = (float*)(sm + SM_MRUN);    // [128]
    float* scale_s = (float*)(sm + SM_SCALE);   // [128]

    const int t    = threadIdx.x;
    const int w    = t >> 5;
    const int lane = t & 31;
    const int l8   = lane & 7;
    const int grp  = lane >> 3;
    const int qr   = lane >> 2;
    const int q2   = (lane & 3) * 2;
    const int wo   = w & 7;      // n-block (phase1) / o-block (phase2)
    const int wh   = w >> 3;     // o-half (phase1) / i-half (phase2)

    // ---- centers: bf16 hi/lo [o][k] + scaled half|c|^2 ----
    {
        const float4* cg4 = (const float4*)cg;
        #pragma unroll
        for (int j = 0; j < 4; j++) {
            int idx = t + j * NTHREADS;
            int r = idx >> 4, c4 = idx & 15;
            float4 v = cg4[idx];
            float h0 = bfl(v.x), h1 = bfl(v.y), h2 = bfl(v.z), h3 = bfl(v.w);
            uint32_t eo = (uint32_t)((r * PK + 4 * c4) * 2);
            *(uint2*)(sm + SM_CHI + eo) = make_uint2(bf2(v.x, v.y), bf2(v.z, v.w));
            *(uint2*)(sm + SM_CLO + eo) = make_uint2(bf2(v.x - h0, v.y - h1), bf2(v.z - h2, v.w - h3));
            float s = v.x*v.x + v.y*v.y + v.z*v.z + v.w*v.w;
            s += __shfl_xor_sync(0xffffffffu, s, 1);
            s += __shfl_xor_sync(0xffffffffu, s, 2);
            s += __shfl_xor_sync(0xffffffffu, s, 4);
            s += __shfl_xor_sync(0xffffffffu, s, 8);
            if ((lane & 15) == 0) half_c2[r] = 0.5f * LOG2E * s;
        }
    }
    if (t < OUTD) m_run[t] = -1e30f;

    // ---- ldmatrix base offsets (bytes) ----
    const uint32_t a1off = (uint32_t)(((16 * wo + l8 + (grp & 1) * 8) * PK + (grp >> 1) * 8) * 2);
    const uint32_t b1off = (uint32_t)(((wh * 64 + (grp >> 1) * 8 + l8) * PK + (grp & 1) * 8) * 2);
    const uint32_t a2off = (uint32_t)((((grp >> 1) * 8 + l8) * PO + 16 * wo + (grp & 1) * 8) * 2);
    const uint32_t b2off = (uint32_t)((lane * PK + wh * 32) * 2);

    float acc2[4][4];
    #pragma unroll
    for (int a = 0; a < 4; a++)
        #pragma unroll
        for (int b = 0; b < 4; b++) acc2[a][b] = 0.f;

    // ---- prologue: load + convert first tile into buf 0 ----
    const int my_tiles = (NTILES - blockIdx.x + NGRID - 1) / NGRID;
    int tile = blockIdx.x;
    {
        const float4* xg4 = (const float4*)(xg + (size_t)tile * TILE * IND);
        float4 xr[4];
        #pragma unroll
        for (int j = 0; j < 4; j++) xr[j] = xg4[t + j * NTHREADS];
        convert_x(xr, sm, 0, t, lane);
    }
    __syncthreads();

    const int o2a = 16 * wo + qr;    // phase-2 o ownership (and +8)

    int cur = 0;
    for (int i = 0; i < my_tiles; i++) {
        const bool have_next = (i + 1 < my_tiles);
        const uint32_t xhi_b = smb + cur * (2 * XBUF);
        const uint32_t xlo_b = xhi_b + XBUF;
        const uint32_t xf_b  = smb + SM_XF16 + cur * XBUF;
        const float* hx2 = (const float*)(sm + SM_HX2) + cur * TILE;

        // issue next tile's global loads early
        float4 xr[4];
        if (have_next) {
            const float4* xg4n = (const float4*)(xg + (size_t)(tile + NGRID) * TILE * IND);
            #pragma unroll
            for (int j = 0; j < 4; j++) xr[j] = xg4n[t + j * NTHREADS];
        }

        // ---- phase 1: D1[16n x 64o] = x . c^T (bf16 hi/lo 3-pass) ----
        uint32_t Ah[4][4], Al[4][4];
        #pragma unroll
        for (int kk = 0; kk < 4; kk++) {
            ldsm4(Ah[kk], xhi_b + a1off + kk * 32);
            ldsm4(Al[kk], xlo_b + a1off + kk * 32);
        }
        float acc1[8][4];
        #pragma unroll
        for (int a = 0; a < 8; a++)
            #pragma unroll
            for (int b = 0; b < 4; b++) acc1[a][b] = 0.f;

        #pragma unroll
        for (int otp = 0; otp < 4; otp++) {
            #pragma unroll
            for (int kk = 0; kk < 4; kk++) {
                uint32_t bh[4], bl[4];
                uint32_t bo = b1off + (uint32_t)(otp * (16 * PK * 2) + kk * 32);
                ldsm4(bh, smb + SM_CHI + bo);
                ldsm4(bl, smb + SM_CLO + bo);
                mma_bf16(acc1[2*otp],   Ah[kk], &bh[0]);
                mma_bf16(acc1[2*otp+1], Ah[kk], &bh[2]);
                mma_bf16(acc1[2*otp],   Ah[kk], &bl[0]);
                mma_bf16(acc1[2*otp+1], Ah[kk], &bl[2]);
                mma_bf16(acc1[2*otp],   Al[kk], &bh[0]);
                mma_bf16(acc1[2*otp+1], Al[kk], &bh[2]);
            }
        }

        // ---- args (log2 rbf) in-place + per-o warp max ----
        const int n0 = 16 * wo + qr;
        {
            const float hx0 = hx2[n0];
            const float hx1 = hx2[n0 + 8];
            #pragma unroll
            for (int ot = 0; ot < 8; ot++) {
                int o0 = wh * 64 + ot * 8 + q2;
                float hc0 = half_c2[o0], hc1 = half_c2[o0 + 1];
                acc1[ot][0] = fmaf(acc1[ot][0], LOG2E, -hx0) - hc0;
                acc1[ot][1] = fmaf(acc1[ot][1], LOG2E, -hx0) - hc1;
                acc1[ot][2] = fmaf(acc1[ot][2], LOG2E, -hx1) - hc0;
                acc1[ot][3] = fmaf(acc1[ot][3], LOG2E, -hx1) - hc1;
            }
            float m0[8], m1[8];
            #pragma unroll
            for (int ot = 0; ot < 8; ot++) {
                m0[ot] = fmaxf(acc1[ot][0], acc1[ot][2]);
                m1[ot] = fmaxf(acc1[ot][1], acc1[ot][3]);
            }
            #pragma unroll
            for (int s = 4; s < 32; s <<= 1) {
                #pragma unroll
                for (int ot = 0; ot < 8; ot++) {
                    m0[ot] = fmaxf(m0[ot], __shfl_xor_sync(0xffffffffu, m0[ot], s));
                    m1[ot] = fmaxf(m1[ot], __shfl_xor_sync(0xffffffffu, m1[ot], s));
                }
            }
            if (lane < 4) {
                #pragma unroll
                for (int ot = 0; ot < 8; ot++) {
                    int o0 = wh * 64 + ot * 8 + q2;
                    m_part[wo * 128 + o0]     = m0[ot];
                    m_part[wo * 128 + o0 + 1] = m1[ot];
                }
            }
        }
        __syncthreads();

        // ---- update running max + rescale factor (threads 0..127) ----
        if (t < OUTD) {
            float m = m_part[t];
            #pragma unroll
            for (int ww = 1; ww < 8; ww++) m = fmaxf(m, m_part[ww * 128 + t]);
            float mo = m_run[t];
            float mn = fmaxf(mo, m);
            m_run[t]   = mn;
            scale_s[t] = exp2f(mo - mn);
        }
        __syncthreads();

        // ---- rescale acc2 to new per-o scale ----
        {
            float s0 = scale_s[o2a];
            float s1 = scale_s[o2a + 8];
            #pragma unroll
            for (int it = 0; it < 4; it++) {
                acc2[it][0] *= s0; acc2[it][1] *= s0;
                acc2[it][2] *= s1; acc2[it][3] *= s1;
            }
        }

        // ---- epilogue: rbf_f16 = 2^(arg - m[o]) ----
        #pragma unroll
        for (int ot = 0; ot < 8; ot++) {
            int o0 = wh * 64 + ot * 8 + q2;
            float mA = m_run[o0], mB = m_run[o0 + 1];
            float v0 = exp2f(acc1[ot][0] - mA);
            float v1 = exp2f(acc1[ot][1] - mB);
            float v2 = exp2f(acc1[ot][2] - mA);
            float v3 = exp2f(acc1[ot][3] - mB);
            *(uint32_t*)(sm + SM_RF16 + (n0 * PO + o0) * 2)       = hf2(v0, v1);
            *(uint32_t*)(sm + SM_RF16 + ((n0 + 8) * PO + o0) * 2) = hf2(v2, v3);
        }
        __syncthreads();   // rbf + scales visible; x[cur] still live

        // convert next tile into the other buffer (overlaps phase-2 MMAs)
        if (have_next) convert_x(xr, sm, cur ^ 1, t, lane);

        // ---- phase 2: hist[16o x 32i] += rbf^T . x  (fp16 single-pass) ----
        #pragma unroll
        for (int kk2 = 0; kk2 < 4; kk2++) {
            uint32_t A2[2][4];
            ldsm4t(A2[0], smb + SM_RF16 + a2off + (2*kk2)     * (16 * PO * 2));
            ldsm4t(A2[1], smb + SM_RF16 + a2off + (2*kk2 + 1) * (16 * PO * 2));
            #pragma unroll
            for (int it = 0; it < 4; it++) {
                uint32_t bh[4];
                ldsm4t(bh, xf_b + b2off + (uint32_t)(kk2 * (32 * PK * 2) + it * 16));
                mma_f16(acc2[it], A2[0], &bh[0]);
                mma_f16(acc2[it], A2[1], &bh[2]);
            }
        }
        __syncthreads();   // next buf ready; rbf free to overwrite

        cur ^= 1;
        tile += NGRID;
    }

    // ---- write out: unscale by 2^m[o]; o = o2a (+8), i = wh*32 + it*8 + q2 (+1) ----
    const float f0 = exp2f(m_run[o2a]);
    const float f1 = exp2f(m_run[o2a + 8]);
    #pragma unroll
    for (int it = 0; it < 4; it++) {
        int i0 = wh * 32 + it * 8 + q2;
        atomicAdd(&out[o2a * IND + i0],           acc2[it][0] * f0);
        atomicAdd(&out[o2a * IND + i0 + 1],       acc2[it][1] * f0);
        atomicAdd(&out[(o2a + 8) * IND + i0],     acc2[it][2] * f1);
        atomicAdd(&out[(o2a + 8) * IND + i0 + 1], acc2[it][3] * f1);
    }
}

extern "C" void kernel_launch(void* const* d_in, const int* in_sizes, int n_in,
                              void* d_out, int out_size) {
    const float* x = (const float*)d_in[0];   // [524288, 64] f32
    const float* c = (const float*)d_in[1];   // [128, 64]    f32
    float* out = (float*)d_out;               // [128, 64]    f32

    cudaFuncSetAttribute(rbf_hist_kernel,
                         cudaFuncAttributeMaxDynamicSharedMemorySize, SMEM_BYTES);

    zero_kernel<<<(OUTD * IND + 255) / 256, 256>>>(out);
    rbf_hist_kernel<<<NGRID, NTHREADS, SMEM_BYTES>>>(x, c, out);
}

// round 15
// speedup vs baseline: 4.6405x; 1.1209x over previous
#include <cuda_runtime.h>
#include <cuda_bf16.h>
#include <cuda_fp16.h>
#include <cstdint>

#define NROWS  524288
#define IND    64
#define OUTD   128
#define TILE   128
#define NTHREADS 512
#define NGRID  148
#define NTILES (NROWS / TILE)   // 4096

#define PK 72     // pitch (elements) of [row][64 k] tiles (b16)
#define PO 136    // pitch (elements) of rbf [n][128 o] (b16)

#define XBUF    (TILE*PK*2)            // 18432 bytes per b16 x tile
#define SM_XF16  (4*XBUF)              // 73728
#define SM_CHI   (SM_XF16 + 2*XBUF)    // 110592
#define SM_CLO   (SM_CHI + XBUF)
#define SM_RF16  (SM_CHI + 2*XBUF)     // 147456 ; fp16 rbf tile
#define SM_MPART (SM_RF16 + TILE*PO*2) // [8][128] f32
#define SM_MRUN  (SM_MPART + 4096)
#define SM_SCALE (SM_MRUN + 512)
#define SM_HX2   (SM_SCALE + 512)
#define SM_HC2   (SM_HX2 + 2*TILE*4)
#define SMEM_BYTES (SM_HC2 + OUTD*4)   // ~188928 bytes

#define LOG2E 1.4426950408889634f

__device__ __forceinline__ uint32_t smem_u32(const void* p) {
    uint32_t a;
    asm("{ .reg .u64 t; cvta.to.shared.u64 t, %1; cvt.u32.u64 %0, t; }" : "=r"(a) : "l"(p));
    return a;
}
__device__ __forceinline__ float ex2(float x) {
    float y; asm("ex2.approx.ftz.f32 %0, %1;" : "=f"(y) : "f"(x)); return y;
}
__device__ __forceinline__ void ldsm4(uint32_t* r, uint32_t addr) {
    asm volatile("ldmatrix.sync.aligned.m8n8.x4.shared.b16 {%0,%1,%2,%3}, [%4];"
        : "=r"(r[0]), "=r"(r[1]), "=r"(r[2]), "=r"(r[3]) : "r"(addr));
}
__device__ __forceinline__ void ldsm4t(uint32_t* r, uint32_t addr) {
    asm volatile("ldmatrix.sync.aligned.m8n8.x4.trans.shared.b16 {%0,%1,%2,%3}, [%4];"
        : "=r"(r[0]), "=r"(r[1]), "=r"(r[2]), "=r"(r[3]) : "r"(addr));
}
__device__ __forceinline__ void mma_bf16(float* d, const uint32_t* a, const uint32_t* b) {
    asm volatile("mma.sync.aligned.m16n8k16.row.col.f32.bf16.bf16.f32 "
        "{%0,%1,%2,%3}, {%4,%5,%6,%7}, {%8,%9}, {%0,%1,%2,%3};"
        : "+f"(d[0]), "+f"(d[1]), "+f"(d[2]), "+f"(d[3])
        : "r"(a[0]), "r"(a[1]), "r"(a[2]), "r"(a[3]), "r"(b[0]), "r"(b[1]));
}
__device__ __forceinline__ void mma_f16(float* d, const uint32_t* a, const uint32_t* b) {
    asm volatile("mma.sync.aligned.m16n8k16.row.col.f32.f16.f16.f32 "
        "{%0,%1,%2,%3}, {%4,%5,%6,%7}, {%8,%9}, {%0,%1,%2,%3};"
        : "+f"(d[0]), "+f"(d[1]), "+f"(d[2]), "+f"(d[3])
        : "r"(a[0]), "r"(a[1]), "r"(a[2]), "r"(a[3]), "r"(b[0]), "r"(b[1]));
}
__device__ __forceinline__ uint32_t bf2(float a, float b) {
    __nv_bfloat162 v = __floats2bfloat162_rn(a, b);
    return *reinterpret_cast<uint32_t*>(&v);
}
__device__ __forceinline__ uint32_t hf2(float a, float b) {
    __half2 v = __floats2half2_rn(a, b);
    return *reinterpret_cast<uint32_t*>(&v);
}
__device__ __forceinline__ float bfl(float a) {
    return __bfloat162float(__float2bfloat16_rn(a));
}

__global__ void zero_kernel(float* out) {
    int i = blockIdx.x * blockDim.x + threadIdx.x;
    if (i < OUTD * IND) out[i] = 0.0f;
}

__device__ __forceinline__ void convert_x(const float4* xr, char* sm, int buf,
                                          int t, int lane) {
    char* xhi = sm + buf * (2 * XBUF);
    char* xlo = xhi + XBUF;
    char* xf  = sm + SM_XF16 + buf * XBUF;
    float* hx2 = (float*)(sm + SM_HX2) + buf * TILE;
    #pragma unroll
    for (int j = 0; j < 4; j++) {
        int idx = t + j * NTHREADS;
        int r = idx >> 4, c4 = idx & 15;
        float4 v = xr[j];
        float h0 = bfl(v.x), h1 = bfl(v.y), h2 = bfl(v.z), h3 = bfl(v.w);
        uint32_t eo = (uint32_t)((r * PK + 4 * c4) * 2);
        *(uint2*)(xhi + eo) = make_uint2(bf2(v.x, v.y), bf2(v.z, v.w));
        *(uint2*)(xlo + eo) = make_uint2(bf2(v.x - h0, v.y - h1), bf2(v.z - h2, v.w - h3));
        *(uint2*)(xf  + eo) = make_uint2(hf2(v.x, v.y), hf2(v.z, v.w));
        float s = v.x*v.x + v.y*v.y + v.z*v.z + v.w*v.w;
        s += __shfl_xor_sync(0xffffffffu, s, 1);
        s += __shfl_xor_sync(0xffffffffu, s, 2);
        s += __shfl_xor_sync(0xffffffffu, s, 4);
        s += __shfl_xor_sync(0xffffffffu, s, 8);
        if ((lane & 15) == 0) hx2[r] = 0.5f * LOG2E * s;
    }
}

__global__ __launch_bounds__(NTHREADS, 1)
void rbf_hist_kernel(const float* __restrict__ xg,
                     const float* __restrict__ cg,
                     float* __restrict__ out) {
    extern __shared__ char sm[];
    const uint32_t smb = smem_u32(sm);
    float* half_c2 = (float*)(sm + SM_HC2);
    float* m_part  = (float*)(sm + SM_MPART);   // [8][128]
    float* m_run   = (float*)(sm + SM_MRUN);    // [128]
    float* scale_s = (float*)(sm + SM_SCALE);   // [128]

    const int t    = threadIdx.x;
    const int w    = t >> 5;
    const int lane = t & 31;
    const int l8   = lane & 7;
    const int grp  = lane >> 3;
    const int qr   = lane >> 2;
    const int q2   = (lane & 3) * 2;
    const int wo   = w & 7;
    const int wh   = w >> 3;

    // ---- centers: bf16 hi/lo [o][k] + scaled half|c|^2 ----
    {
        const float4* cg4 = (const float4*)cg;
        #pragma unroll
        for (int j = 0; j < 4; j++) {
            int idx = t + j * NTHREADS;
            int r = idx >> 4, c4 = idx & 15;
            float4 v = cg4[idx];
            float h0 = bfl(v.x), h1 = bfl(v.y), h2 = bfl(v.z), h3 = bfl(v.w);
            uint32_t eo = (uint32_t)((r * PK + 4 * c4) * 2);
            *(uint2*)(sm + SM_CHI + eo) = make_uint2(bf2(v.x, v.y), bf2(v.z, v.w));
            *(uint2*)(sm + SM_CLO + eo) = make_uint2(bf2(v.x - h0, v.y - h1), bf2(v.z - h2, v.w - h3));
            float s = v.x*v.x + v.y*v.y + v.z*v.z + v.w*v.w;
            s += __shfl_xor_sync(0xffffffffu, s, 1);
            s += __shfl_xor_sync(0xffffffffu, s, 2);
            s += __shfl_xor_sync(0xffffffffu, s, 4);
            s += __shfl_xor_sync(0xffffffffu, s, 8);
            if ((lane & 15) == 0) half_c2[r] = 0.5f * LOG2E * s;
        }
    }
    if (t < OUTD) m_run[t] = -1e30f;

    const uint32_t a1off = (uint32_t)(((16 * wo + l8 + (grp & 1) * 8) * PK + (grp >> 1) * 8) * 2);
    const uint32_t b1off = (uint32_t)(((wh * 64 + (grp >> 1) * 8 + l8) * PK + (grp & 1) * 8) * 2);
    const uint32_t a2off = (uint32_t)((((grp >> 1) * 8 + l8) * PO + 16 * wo + (grp & 1) * 8) * 2);
    const uint32_t b2off = (uint32_t)((lane * PK + wh * 32) * 2);

    float acc2[4][4];
    #pragma unroll
    for (int a = 0; a < 4; a++)
        #pragma unroll
        for (int b = 0; b < 4; b++) acc2[a][b] = 0.f;

    const int my_tiles = (NTILES - blockIdx.x + NGRID - 1) / NGRID;
    int tile = blockIdx.x;
    {
        const float4* xg4 = (const float4*)(xg + (size_t)tile * TILE * IND);
        float4 xr[4];
        #pragma unroll
        for (int j = 0; j < 4; j++) xr[j] = xg4[t + j * NTHREADS];
        convert_x(xr, sm, 0, t, lane);
    }
    __syncthreads();

    const int o2a = 16 * wo + qr;

    int cur = 0;
    for (int i = 0; i < my_tiles; i++) {
        const bool have_next = (i + 1 < my_tiles);
        const uint32_t xhi_b = smb + cur * (2 * XBUF);
        const uint32_t xlo_b = xhi_b + XBUF;
        const uint32_t xf_b  = smb + SM_XF16 + cur * XBUF;
        const float* hx2 = (const float*)(sm + SM_HX2) + cur * TILE;

        float4 xr[4];
        if (have_next) {
            const float4* xg4n = (const float4*)(xg + (size_t)(tile + NGRID) * TILE * IND);
            #pragma unroll
            for (int j = 0; j < 4; j++) xr[j] = xg4n[t + j * NTHREADS];
        }

        // ---- phase 1: ILP-scheduled (o-block pairs, same-acc distance 4) ----
        uint32_t Ah[4][4], Al[4][4];
        #pragma unroll
        for (int kk = 0; kk < 4; kk++) {
            ldsm4(Ah[kk], xhi_b + a1off + kk * 32);
            ldsm4(Al[kk], xlo_b + a1off + kk * 32);
        }
        float acc1[8][4];
        #pragma unroll
        for (int a = 0; a < 8; a++)
            #pragma unroll
            for (int b = 0; b < 4; b++) acc1[a][b] = 0.f;

        #pragma unroll
        for (int op2 = 0; op2 < 2; op2++) {
            float* a0 = acc1[4 * op2 + 0];
            float* a1 = acc1[4 * op2 + 1];
            float* a2 = acc1[4 * op2 + 2];
            float* a3 = acc1[4 * op2 + 3];
            #pragma unroll
            for (int kk = 0; kk < 4; kk++) {
                uint32_t b0h[4], b0l[4], b1h[4], b1l[4];
                uint32_t bo0 = b1off + (uint32_t)((2*op2)   * (16 * PK * 2) + kk * 32);
                uint32_t bo1 = b1off + (uint32_t)((2*op2+1) * (16 * PK * 2) + kk * 32);
                ldsm4(b0h, smb + SM_CHI + bo0);
                ldsm4(b0l, smb + SM_CLO + bo0);
                ldsm4(b1h, smb + SM_CHI + bo1);
                ldsm4(b1l, smb + SM_CLO + bo1);
                // sweep hi*hi
                mma_bf16(a0, Ah[kk], &b0h[0]);
                mma_bf16(a1, Ah[kk], &b0h[2]);
                mma_bf16(a2, Ah[kk], &b1h[0]);
                mma_bf16(a3, Ah[kk], &b1h[2]);
                // sweep hi*lo
                mma_bf16(a0, Ah[kk], &b0l[0]);
                mma_bf16(a1, Ah[kk], &b0l[2]);
                mma_bf16(a2, Ah[kk], &b1l[0]);
                mma_bf16(a3, Ah[kk], &b1l[2]);
                // sweep lo*hi
                mma_bf16(a0, Al[kk], &b0h[0]);
                mma_bf16(a1, Al[kk], &b0h[2]);
                mma_bf16(a2, Al[kk], &b1h[0]);
                mma_bf16(a3, Al[kk], &b1h[2]);
            }
        }

        // ---- args (log2 rbf) + pair-max reduction ----
        const int n0 = 16 * wo + qr;
        {
            const float hx0 = hx2[n0];
            const float hx1 = hx2[n0 + 8];
            #pragma unroll
            for (int ot = 0; ot < 8; ot++) {
                int o0 = wh * 64 + ot * 8 + q2;
                float hc0 = half_c2[o0], hc1 = half_c2[o0 + 1];
                acc1[ot][0] = fmaf(acc1[ot][0], LOG2E, -hx0) - hc0;
                acc1[ot][1] = fmaf(acc1[ot][1], LOG2E, -hx0) - hc1;
                acc1[ot][2] = fmaf(acc1[ot][2], LOG2E, -hx1) - hc0;
                acc1[ot][3] = fmaf(acc1[ot][3], LOG2E, -hx1) - hc1;
            }
            // pair max (o0 and o0+1 share one scale)
            float m01[8];
            #pragma unroll
            for (int ot = 0; ot < 8; ot++)
                m01[ot] = fmaxf(fmaxf(acc1[ot][0], acc1[ot][2]),
                                fmaxf(acc1[ot][1], acc1[ot][3]));
            #pragma unroll
            for (int s = 4; s < 32; s <<= 1)
                #pragma unroll
                for (int ot = 0; ot < 8; ot++)
                    m01[ot] = fmaxf(m01[ot], __shfl_xor_sync(0xffffffffu, m01[ot], s));
            if (lane < 4) {
                #pragma unroll
                for (int ot = 0; ot < 8; ot++) {
                    int o0 = wh * 64 + ot * 8 + q2;
                    m_part[wo * 128 + o0]     = m01[ot];
                    m_part[wo * 128 + o0 + 1] = m01[ot];
                }
            }
        }
        __syncthreads();

        if (t < OUTD) {
            float m = m_part[t];
            #pragma unroll
            for (int ww = 1; ww < 8; ww++) m = fmaxf(m, m_part[ww * 128 + t]);
            float mo = m_run[t];
            float mn = fmaxf(mo, m);
            m_run[t]   = mn;
            scale_s[t] = ex2(mo - mn);
        }
        __syncthreads();

        {
            float s0 = scale_s[o2a];
            float s1 = scale_s[o2a + 8];
            #pragma unroll
            for (int it = 0; it < 4; it++) {
                acc2[it][0] *= s0; acc2[it][1] *= s0;
                acc2[it][2] *= s1; acc2[it][3] *= s1;
            }
        }

        // ---- epilogue: rbf_f16 = 2^(arg - m[o]) ----
        #pragma unroll
        for (int ot = 0; ot < 8; ot++) {
            int o0 = wh * 64 + ot * 8 + q2;
            float mA = m_run[o0], mB = m_run[o0 + 1];
            float v0 = ex2(acc1[ot][0] - mA);
            float v1 = ex2(acc1[ot][1] - mB);
            float v2 = ex2(acc1[ot][2] - mA);
            float v3 = ex2(acc1[ot][3] - mB);
            *(uint32_t*)(sm + SM_RF16 + (n0 * PO + o0) * 2)       = hf2(v0, v1);
            *(uint32_t*)(sm + SM_RF16 + ((n0 + 8) * PO + o0) * 2) = hf2(v2, v3);
        }
        __syncthreads();

        if (have_next) convert_x(xr, sm, cur ^ 1, t, lane);

        // ---- phase 2: ILP-scheduled (same-acc distance 4) ----
        #pragma unroll
        for (int kk2 = 0; kk2 < 4; kk2++) {
            uint32_t A2[2][4];
            ldsm4t(A2[0], smb + SM_RF16 + a2off + (2*kk2)     * (16 * PO * 2));
            ldsm4t(A2[1], smb + SM_RF16 + a2off + (2*kk2 + 1) * (16 * PO * 2));
            uint32_t bh[4][4];
            #pragma unroll
            for (int it = 0; it < 4; it++)
                ldsm4t(bh[it], xf_b + b2off + (uint32_t)(kk2 * (32 * PK * 2) + it * 16));
            #pragma unroll
            for (int it = 0; it < 4; it++)
                mma_f16(acc2[it], A2[0], &bh[it][0]);
            #pragma unroll
            for (int it = 0; it < 4; it++)
                mma_f16(acc2[it], A2[1], &bh[it][2]);
        }
        __syncthreads();

        cur ^= 1;
        tile += NGRID;
    }

    // ---- write out: unscale by 2^m[o] ----
    const float f0 = exp2f(m_run[o2a]);
    const float f1 = exp2f(m_run[o2a + 8]);
    #pragma unroll
    for (int it = 0; it < 4; it++) {
        int i0 = wh * 32 + it * 8 + q2;
        atomicAdd(&out[o2a * IND + i0],           acc2[it][0] * f0);
        atomicAdd(&out[o2a * IND + i0 + 1],       acc2[it][1] * f0);
        atomicAdd(&out[(o2a + 8) * IND + i0],     acc2[it][2] * f1);
        atomicAdd(&out[(o2a + 8) * IND + i0 + 1], acc2[it][3] * f1);
    }
}

extern "C" void kernel_launch(void* const* d_in, const int* in_sizes, int n_in,
                              void* d_out, int out_size) {
    const float* x = (const float*)d_in[0];   // [524288, 64] f32
    const float* c = (const float*)d_in[1];   // [128, 64]    f32
    float* out = (float*)d_out;               // [128, 64]    f32

    cudaFuncSetAttribute(rbf_hist_kernel,
                         cudaFuncAttributeMaxDynamicSharedMemorySize, SMEM_BYTES);

    zero_kernel<<<(OUTD * IND + 255) / 256, 256>>>(out);
    rbf_hist_kernel<<<NGRID, NTHREADS, SMEM_BYTES>>>(x, c, out);
}